// round 1
// baseline (speedup 1.0000x reference)
#include <cuda_runtime.h>

#define BB 4
#define NN 4096
#define CC 1024
#define NH 8
#define HC 128
#define OO 2048
#define NSEG 8

// Scratch (device globals; no allocation allowed)
__device__ float g_Q[BB*CC*NN];
__device__ float g_K[BB*CC*NN];
__device__ float g_V[BB*CC*NN];
__device__ float g_att[BB*CC*NN];
__device__ float g_S[BB*NH*HC*HC];
__device__ float g_Sp[NSEG*BB*NH*HC*HC];
__device__ float g_y[BB*NN*OO];
__device__ float g_cmax[BB*CC];
__device__ float g_cinv[BB*CC];

// ---------------------------------------------------------------------------
// 1) Column softmax stats for "key": per (b, ch) max & 1/sumexp over N tokens
// ---------------------------------------------------------------------------
__global__ void colstats_k(const float* __restrict__ x2) {
    int b = blockIdx.y;
    int ch = blockIdx.x * 32 + threadIdx.x;
    const float* p = x2 + b * NN * CC + ch;
    float m = -1e30f, s = 0.f;
    for (int n = threadIdx.y; n < NN; n += 8) {
        float v = p[n * CC];
        float mn = fmaxf(m, v);
        s = s * __expf(m - mn) + __expf(v - mn);
        m = mn;
    }
    __shared__ float sm[8][32], ss[8][32];
    sm[threadIdx.y][threadIdx.x] = m;
    ss[threadIdx.y][threadIdx.x] = s;
    __syncthreads();
    if (threadIdx.y == 0) {
        for (int r = 1; r < 8; r++) {
            float m2 = sm[r][threadIdx.x], s2 = ss[r][threadIdx.x];
            float mn = fmaxf(m, m2);
            s = s * __expf(m - mn) + s2 * __expf(m2 - mn);
            m = mn;
        }
        g_cmax[b * CC + ch] = m;
        g_cinv[b * CC + ch] = 1.f / s;
    }
}

// ---------------------------------------------------------------------------
// 2) Prep: read x1/x2 tiles (32 tokens x 128 ch), compute query softmax (over
//    ch) and key softmax (column stats), write Q, K, V transposed to [b,h,c,N]
//    — coalesced reads AND writes via smem transpose.
// ---------------------------------------------------------------------------
__global__ void prep_k(const float* __restrict__ x1, const float* __restrict__ x2) {
    __shared__ float t[HC][33];
    __shared__ float tmx[32], tsi[32];
    int b = blockIdx.y, n0 = blockIdx.x * 32;
    int tid = threadIdx.x;
    int w = tid >> 5, l = tid & 31;
    for (int hd = 0; hd < NH; hd++) {
        const float* src = x2 + (b * NN + n0) * CC + hd * HC;
        #pragma unroll
        for (int k = 0; k < 16; k++) {
            int e = tid + 256 * k; int i = e & 127, tt = e >> 7;
            t[i][tt] = src[tt * CC + i];
        }
        __syncthreads();
        // query softmax over the 128 per-head channels, one warp -> 4 tokens
        #pragma unroll
        for (int q = 0; q < 4; q++) {
            int tok = w * 4 + q;
            float v0 = t[l][tok], v1 = t[l + 32][tok], v2 = t[l + 64][tok], v3 = t[l + 96][tok];
            float m = fmaxf(fmaxf(v0, v1), fmaxf(v2, v3));
            #pragma unroll
            for (int o = 16; o; o >>= 1) m = fmaxf(m, __shfl_xor_sync(0xffffffffu, m, o));
            float s = __expf(v0 - m) + __expf(v1 - m) + __expf(v2 - m) + __expf(v3 - m);
            #pragma unroll
            for (int o = 16; o; o >>= 1) s += __shfl_xor_sync(0xffffffffu, s, o);
            if (l == 0) { tmx[tok] = m; tsi[tok] = 1.f / s; }
        }
        __syncthreads();
        float* Qd = g_Q + (b * NH + hd) * HC * NN + n0;
        float* Kd = g_K + (b * NH + hd) * HC * NN + n0;
        const float* cm = g_cmax + b * CC + hd * HC;
        const float* ci = g_cinv + b * CC + hd * HC;
        #pragma unroll
        for (int k = 0; k < 16; k++) {
            int e = tid + 256 * k; int tt = e & 31, i = e >> 5;
            float v = t[i][tt];
            Qd[i * NN + tt] = __expf(v - tmx[tt]) * tsi[tt];
            Kd[i * NN + tt] = __expf(v - cm[i]) * ci[i];
        }
        __syncthreads();
        const float* sv = x1 + (b * NN + n0) * CC + hd * HC;
        #pragma unroll
        for (int k = 0; k < 16; k++) {
            int e = tid + 256 * k; int i = e & 127, tt = e >> 7;
            t[i][tt] = sv[tt * CC + i];
        }
        __syncthreads();
        float* Vd = g_V + (b * NH + hd) * HC * NN + n0;
        #pragma unroll
        for (int k = 0; k < 16; k++) {
            int e = tid + 256 * k; int tt = e & 31, i = e >> 5;
            Vd[i * NN + tt] = t[i][tt];
        }
        __syncthreads();
    }
}

// ---------------------------------------------------------------------------
// Shared 128x128-tile, 8x8-per-thread fp32 microkernel
// ---------------------------------------------------------------------------
__device__ __forceinline__ void tile_fma(const float (&As)[32][132], const float (&Bs)[32][132],
                                         float (&acc)[8][8], int tx, int ty) {
    #pragma unroll
    for (int kk = 0; kk < 32; kk++) {
        float4 a0 = *(const float4*)&As[kk][ty * 8];
        float4 a1 = *(const float4*)&As[kk][ty * 8 + 4];
        float4 b0 = *(const float4*)&Bs[kk][tx * 8];
        float4 b1 = *(const float4*)&Bs[kk][tx * 8 + 4];
        float av[8] = {a0.x, a0.y, a0.z, a0.w, a1.x, a1.y, a1.z, a1.w};
        float bv[8] = {b0.x, b0.y, b0.z, b0.w, b1.x, b1.y, b1.z, b1.w};
        #pragma unroll
        for (int u = 0; u < 8; u++)
            #pragma unroll
            for (int v = 0; v < 8; v++)
                acc[u][v] = fmaf(av[u], bv[v], acc[u][v]);
    }
}

// ---------------------------------------------------------------------------
// 3) GEMM1 (split-K, deterministic partials): Sp[seg] = Q[:,seg] * K[:,seg]^T
// ---------------------------------------------------------------------------
__global__ void __launch_bounds__(256, 2) gemm1_k() {
    __shared__ float As[32][132], Bs[32][132];
    int seg = blockIdx.x, bh = blockIdx.y;
    int tid = threadIdx.x, tx = tid & 15, ty = tid >> 4;
    const float* A = g_Q + bh * HC * NN;
    const float* Bm = g_K + bh * HC * NN;
    float acc[8][8] = {};
    int nb = seg * (NN / NSEG);
    for (int it = 0; it < (NN / NSEG) / 32; it++) {
        int k0 = nb + it * 32;
        #pragma unroll
        for (int k = 0; k < 16; k++) {
            int e = tid + 256 * k; int kk = e & 31, i = e >> 5;
            As[kk][i] = A[i * NN + k0 + kk];
            Bs[kk][i] = Bm[i * NN + k0 + kk];
        }
        __syncthreads();
        tile_fma(As, Bs, acc, tx, ty);
        __syncthreads();
    }
    float* out = g_Sp + (seg * BB * NH + bh) * HC * HC;
    #pragma unroll
    for (int u = 0; u < 8; u++) {
        float4 c0 = {acc[u][0], acc[u][1], acc[u][2], acc[u][3]};
        float4 c1 = {acc[u][4], acc[u][5], acc[u][6], acc[u][7]};
        *(float4*)&out[(ty * 8 + u) * HC + tx * 8] = c0;
        *(float4*)&out[(ty * 8 + u) * HC + tx * 8 + 4] = c1;
    }
}

__global__ void reduceS_k() {
    int i = blockIdx.x * 256 + threadIdx.x;
    float s = 0.f;
    #pragma unroll
    for (int r = 0; r < NSEG; r++) s += g_Sp[r * (BB * NH * HC * HC) + i];
    g_S[i] = s;
}

// ---------------------------------------------------------------------------
// 4) GEMM2: att = S * V   ([128x128] @ [128x4096] per (b,h))
// ---------------------------------------------------------------------------
__global__ void __launch_bounds__(256, 2) gemm2_k() {
    __shared__ float As[32][132], Bs[32][132];
    int n0 = blockIdx.x * 128, bh = blockIdx.y;
    int tid = threadIdx.x, tx = tid & 15, ty = tid >> 4;
    const float* A = g_S + bh * HC * HC;   // [i][j]
    const float* Bm = g_V + bh * HC * NN;  // [j][n]
    float acc[8][8] = {};
    for (int it = 0; it < HC / 32; it++) {
        int k0 = it * 32;
        #pragma unroll
        for (int k = 0; k < 16; k++) {
            int e = tid + 256 * k; int kk = e & 31, i = e >> 5;
            As[kk][i] = A[i * HC + k0 + kk];
        }
        #pragma unroll
        for (int k = 0; k < 16; k++) {
            int e = tid + 256 * k; int tt = e & 127, kk = e >> 7;
            Bs[kk][tt] = Bm[(k0 + kk) * NN + n0 + tt];
        }
        __syncthreads();
        tile_fma(As, Bs, acc, tx, ty);
        __syncthreads();
    }
    float* out = g_att + bh * HC * NN + n0;
    #pragma unroll
    for (int u = 0; u < 8; u++) {
        float4 c0 = {acc[u][0], acc[u][1], acc[u][2], acc[u][3]};
        float4 c1 = {acc[u][4], acc[u][5], acc[u][6], acc[u][7]};
        *(float4*)&out[(ty * 8 + u) * NN + tx * 8] = c0;
        *(float4*)&out[(ty * 8 + u) * NN + tx * 8 + 4] = c1;
    }
}

// ---------------------------------------------------------------------------
// 5) GEMM3 (dominant): y[b,n,o] = sum_ch w[o,ch] * agg[b,ch,n]
// ---------------------------------------------------------------------------
__global__ void __launch_bounds__(256, 2) gemm3_k(const float* __restrict__ w) {
    __shared__ float As[32][132], Bs[32][132];
    int n0 = blockIdx.x * 128, o0 = blockIdx.y * 128, b = blockIdx.z;
    int tid = threadIdx.x, tx = tid & 15, ty = tid >> 4;
    const float* A = g_att + b * CC * NN;  // [ch][n]
    float acc[8][8] = {};
    for (int it = 0; it < CC / 32; it++) {
        int k0 = it * 32;
        #pragma unroll
        for (int k = 0; k < 16; k++) {
            int e = tid + 256 * k; int tt = e & 127, kk = e >> 7;
            As[kk][tt] = A[(k0 + kk) * NN + n0 + tt];
        }
        #pragma unroll
        for (int k = 0; k < 16; k++) {
            int e = tid + 256 * k; int kk = e & 31, oo = e >> 5;
            Bs[kk][oo] = w[(o0 + oo) * CC + k0 + kk];
        }
        __syncthreads();
        tile_fma(As, Bs, acc, tx, ty);
        __syncthreads();
    }
    float* out = g_y + (b * NN + n0) * OO + o0;
    #pragma unroll
    for (int u = 0; u < 8; u++) {
        float4 c0 = {acc[u][0], acc[u][1], acc[u][2], acc[u][3]};
        float4 c1 = {acc[u][4], acc[u][5], acc[u][6], acc[u][7]};
        *(float4*)&out[(ty * 8 + u) * OO + tx * 8] = c0;
        *(float4*)&out[(ty * 8 + u) * OO + tx * 8 + 4] = c1;
    }
}

// ---------------------------------------------------------------------------
// 6) Fused bias + LayerNorm over O=2048, one block per token
// ---------------------------------------------------------------------------
__global__ void ln_k(float* __restrict__ out, const float* __restrict__ bp,
                     const float* __restrict__ gm, const float* __restrict__ bt) {
    int t = blockIdx.x;
    const float* y = g_y + t * OO;
    int tid = threadIdx.x;
    float v[8];
    float s = 0.f, sq = 0.f;
    #pragma unroll
    for (int k = 0; k < 8; k++) {
        int o = tid + 256 * k;
        float x = y[o] + bp[o];
        v[k] = x; s += x; sq += x * x;
    }
    #pragma unroll
    for (int o = 16; o; o >>= 1) {
        s += __shfl_xor_sync(0xffffffffu, s, o);
        sq += __shfl_xor_sync(0xffffffffu, sq, o);
    }
    __shared__ float rs[8], rq[8];
    if ((tid & 31) == 0) { rs[tid >> 5] = s; rq[tid >> 5] = sq; }
    __syncthreads();
    if (tid < 8) {
        float a = rs[tid], b2 = rq[tid];
        #pragma unroll
        for (int o = 4; o; o >>= 1) {
            a += __shfl_xor_sync(0x000000ffu, a, o);
            b2 += __shfl_xor_sync(0x000000ffu, b2, o);
        }
        if (tid == 0) { rs[0] = a; rq[0] = b2; }
    }
    __syncthreads();
    float mean = rs[0] * (1.f / OO);
    float var = rq[0] * (1.f / OO) - mean * mean;
    float rstd = rsqrtf(var + 1e-5f);
    float* op = out + t * OO;
    #pragma unroll
    for (int k = 0; k < 8; k++) {
        int o = tid + 256 * k;
        op[o] = (v[k] - mean) * rstd * gm[o] + bt[o];
    }
}

extern "C" void kernel_launch(void* const* d_in, const int* in_sizes, int n_in,
                              void* d_out, int out_size) {
    const float* x1 = (const float*)d_in[0];
    const float* x2 = (const float*)d_in[1];
    const float* w  = (const float*)d_in[2];
    const float* bp = (const float*)d_in[3];
    const float* gm = (const float*)d_in[4];
    const float* bt = (const float*)d_in[5];
    float* out = (float*)d_out;

    colstats_k<<<dim3(CC / 32, BB), dim3(32, 8)>>>(x2);
    prep_k<<<dim3(NN / 32, BB), 256>>>(x1, x2);
    gemm1_k<<<dim3(NSEG, BB * NH), 256>>>();
    reduceS_k<<<(BB * NH * HC * HC) / 256, 256>>>();
    gemm2_k<<<dim3(NN / 128, BB * NH), 256>>>();
    gemm3_k<<<dim3(NN / 128, OO / 128, BB), 256>>>(w);
    ln_k<<<BB * NN, 256>>>(out, bp, gm, bt);
}

// round 2
// speedup vs baseline: 1.2702x; 1.2702x over previous
#include <cuda_runtime.h>
#include <mma.h>

using namespace nvcuda;

#define BB 4
#define NN 4096
#define CC 1024
#define NH 8
#define HC 128
#define OO 2048
#define NSEG 8
#define LDS 136   // padded leading dim for smem tiles (k-major [32][136])

// Scratch (device globals; no allocation allowed)
__device__ float g_Q[BB*CC*NN];
__device__ float g_K[BB*CC*NN];
__device__ float g_V[BB*CC*NN];
__device__ float g_att[BB*CC*NN];
__device__ float g_S[BB*NH*HC*HC];
__device__ float g_Sp[NSEG*BB*NH*HC*HC];
__device__ float g_y[BB*NN*OO];
__device__ float g_cmax[BB*CC];
__device__ float g_cinv[BB*CC];

// ---------------------------------------------------------------------------
// 1) Column softmax stats for "key": per (b, ch) max & 1/sumexp over N tokens
// ---------------------------------------------------------------------------
__global__ void colstats_k(const float* __restrict__ x2) {
    int b = blockIdx.y;
    int ch = blockIdx.x * 32 + threadIdx.x;
    const float* p = x2 + b * NN * CC + ch;
    float m = -1e30f, s = 0.f;
    for (int n = threadIdx.y; n < NN; n += 8) {
        float v = p[n * CC];
        float mn = fmaxf(m, v);
        s = s * __expf(m - mn) + __expf(v - mn);
        m = mn;
    }
    __shared__ float sm[8][32], ss[8][32];
    sm[threadIdx.y][threadIdx.x] = m;
    ss[threadIdx.y][threadIdx.x] = s;
    __syncthreads();
    if (threadIdx.y == 0) {
        for (int r = 1; r < 8; r++) {
            float m2 = sm[r][threadIdx.x], s2 = ss[r][threadIdx.x];
            float mn = fmaxf(m, m2);
            s = s * __expf(m - mn) + s2 * __expf(m2 - mn);
            m = mn;
        }
        g_cmax[b * CC + ch] = m;
        g_cinv[b * CC + ch] = 1.f / s;
    }
}

// ---------------------------------------------------------------------------
// 2) Prep: transpose + both softmaxes, writing Q, K, V as [b,h,c,N]
// ---------------------------------------------------------------------------
__global__ void prep_k(const float* __restrict__ x1, const float* __restrict__ x2) {
    __shared__ float t[HC][33];
    __shared__ float tmx[32], tsi[32];
    int b = blockIdx.y, n0 = blockIdx.x * 32;
    int tid = threadIdx.x;
    int w = tid >> 5, l = tid & 31;
    for (int hd = 0; hd < NH; hd++) {
        const float* src = x2 + (b * NN + n0) * CC + hd * HC;
        #pragma unroll
        for (int k = 0; k < 16; k++) {
            int e = tid + 256 * k; int i = e & 127, tt = e >> 7;
            t[i][tt] = src[tt * CC + i];
        }
        __syncthreads();
        #pragma unroll
        for (int q = 0; q < 4; q++) {
            int tok = w * 4 + q;
            float v0 = t[l][tok], v1 = t[l + 32][tok], v2 = t[l + 64][tok], v3 = t[l + 96][tok];
            float m = fmaxf(fmaxf(v0, v1), fmaxf(v2, v3));
            #pragma unroll
            for (int o = 16; o; o >>= 1) m = fmaxf(m, __shfl_xor_sync(0xffffffffu, m, o));
            float s = __expf(v0 - m) + __expf(v1 - m) + __expf(v2 - m) + __expf(v3 - m);
            #pragma unroll
            for (int o = 16; o; o >>= 1) s += __shfl_xor_sync(0xffffffffu, s, o);
            if (l == 0) { tmx[tok] = m; tsi[tok] = 1.f / s; }
        }
        __syncthreads();
        float* Qd = g_Q + (b * NH + hd) * HC * NN + n0;
        float* Kd = g_K + (b * NH + hd) * HC * NN + n0;
        const float* cm = g_cmax + b * CC + hd * HC;
        const float* ci = g_cinv + b * CC + hd * HC;
        #pragma unroll
        for (int k = 0; k < 16; k++) {
            int e = tid + 256 * k; int tt = e & 31, i = e >> 5;
            float v = t[i][tt];
            Qd[i * NN + tt] = __expf(v - tmx[tt]) * tsi[tt];
            Kd[i * NN + tt] = __expf(v - cm[i]) * ci[i];
        }
        __syncthreads();
        const float* sv = x1 + (b * NN + n0) * CC + hd * HC;
        #pragma unroll
        for (int k = 0; k < 16; k++) {
            int e = tid + 256 * k; int i = e & 127, tt = e >> 7;
            t[i][tt] = sv[tt * CC + i];
        }
        __syncthreads();
        float* Vd = g_V + (b * NH + hd) * HC * NN + n0;
        #pragma unroll
        for (int k = 0; k < 16; k++) {
            int e = tid + 256 * k; int tt = e & 31, i = e >> 5;
            Vd[i * NN + tt] = t[i][tt];
        }
        __syncthreads();
    }
}

// ---------------------------------------------------------------------------
// Shared tf32 wmma microkernel: smem layout As[k][m] (col_major A) and
// Bs[k][n] (row_major B), both [32][LDS]. 8 warps: warp tile 32(m) x 64(n).
// ---------------------------------------------------------------------------
typedef wmma::fragment<wmma::matrix_a, 16, 16, 8, wmma::precision::tf32, wmma::col_major> FragA;
typedef wmma::fragment<wmma::matrix_b, 16, 16, 8, wmma::precision::tf32, wmma::row_major> FragB;
typedef wmma::fragment<wmma::accumulator, 16, 16, 8, float> FragC;

__device__ __forceinline__ void wmma_tile(const float* As, const float* Bs,
                                          FragC (&acc)[2][4], int wm, int wn) {
    #pragma unroll
    for (int kt = 0; kt < 4; kt++) {
        FragA a[2];
        FragB bfr[4];
        #pragma unroll
        for (int mi = 0; mi < 2; mi++) {
            wmma::load_matrix_sync(a[mi], As + (kt * 8) * LDS + wm * 32 + mi * 16, LDS);
            #pragma unroll
            for (int e = 0; e < a[mi].num_elements; e++)
                a[mi].x[e] = wmma::__float_to_tf32(a[mi].x[e]);
        }
        #pragma unroll
        for (int ni = 0; ni < 4; ni++) {
            wmma::load_matrix_sync(bfr[ni], Bs + (kt * 8) * LDS + wn * 64 + ni * 16, LDS);
            #pragma unroll
            for (int e = 0; e < bfr[ni].num_elements; e++)
                bfr[ni].x[e] = wmma::__float_to_tf32(bfr[ni].x[e]);
        }
        #pragma unroll
        for (int mi = 0; mi < 2; mi++)
            #pragma unroll
            for (int ni = 0; ni < 4; ni++)
                wmma::mma_sync(acc[mi][ni], a[mi], bfr[ni], acc[mi][ni]);
    }
}

__device__ __forceinline__ void store_tile(float* out, int ld, FragC (&acc)[2][4],
                                           int wm, int wn) {
    #pragma unroll
    for (int mi = 0; mi < 2; mi++)
        #pragma unroll
        for (int ni = 0; ni < 4; ni++)
            wmma::store_matrix_sync(out + (wm * 32 + mi * 16) * ld + wn * 64 + ni * 16,
                                    acc[mi][ni], ld, wmma::mem_row_major);
}

// ---------------------------------------------------------------------------
// 3) GEMM1 (split-K): Sp[seg] = Q[:,seg] * K[:,seg]^T   (tf32 tensor cores)
// ---------------------------------------------------------------------------
__global__ void __launch_bounds__(256, 2) gemm1_k() {
    __shared__ float As[32][LDS], Bs[32][LDS];
    int seg = blockIdx.x, bh = blockIdx.y;
    int tid = threadIdx.x;
    int wid = tid >> 5, wm = wid >> 1, wn = wid & 1;
    const float* A = g_Q + bh * HC * NN;
    const float* Bm = g_K + bh * HC * NN;
    FragC acc[2][4];
    #pragma unroll
    for (int mi = 0; mi < 2; mi++)
        #pragma unroll
        for (int ni = 0; ni < 4; ni++) wmma::fill_fragment(acc[mi][ni], 0.f);
    int nb = seg * (NN / NSEG);
    for (int it = 0; it < (NN / NSEG) / 32; it++) {
        int k0 = nb + it * 32;
        #pragma unroll
        for (int k = 0; k < 16; k++) {
            int e = tid + 256 * k; int kk = e & 31, i = e >> 5;
            As[kk][i] = A[i * NN + k0 + kk];
            Bs[kk][i] = Bm[i * NN + k0 + kk];
        }
        __syncthreads();
        wmma_tile(&As[0][0], &Bs[0][0], acc, wm, wn);
        __syncthreads();
    }
    float* out = g_Sp + (seg * BB * NH + bh) * HC * HC;
    store_tile(out, HC, acc, wm, wn);
}

__global__ void reduceS_k() {
    int i = blockIdx.x * 256 + threadIdx.x;
    float s = 0.f;
    #pragma unroll
    for (int r = 0; r < NSEG; r++) s += g_Sp[r * (BB * NH * HC * HC) + i];
    g_S[i] = s;
}

// ---------------------------------------------------------------------------
// 4) GEMM2: att = S * V   (tf32 tensor cores)
// ---------------------------------------------------------------------------
__global__ void __launch_bounds__(256, 2) gemm2_k() {
    __shared__ float As[32][LDS], Bs[32][LDS];
    int n0 = blockIdx.x * 128, bh = blockIdx.y;
    int tid = threadIdx.x;
    int wid = tid >> 5, wm = wid >> 1, wn = wid & 1;
    const float* A = g_S + bh * HC * HC;   // [i][j]
    const float* Bm = g_V + bh * HC * NN;  // [j][n]
    FragC acc[2][4];
    #pragma unroll
    for (int mi = 0; mi < 2; mi++)
        #pragma unroll
        for (int ni = 0; ni < 4; ni++) wmma::fill_fragment(acc[mi][ni], 0.f);
    for (int it = 0; it < HC / 32; it++) {
        int k0 = it * 32;
        #pragma unroll
        for (int k = 0; k < 16; k++) {
            int e = tid + 256 * k; int kk = e & 31, i = e >> 5;
            As[kk][i] = A[i * HC + k0 + kk];
        }
        #pragma unroll
        for (int k = 0; k < 16; k++) {
            int e = tid + 256 * k; int tt = e & 127, kk = e >> 7;
            Bs[kk][tt] = Bm[(k0 + kk) * NN + n0 + tt];
        }
        __syncthreads();
        wmma_tile(&As[0][0], &Bs[0][0], acc, wm, wn);
        __syncthreads();
    }
    float* out = g_att + bh * HC * NN + n0;
    store_tile(out, NN, acc, wm, wn);
}

// ---------------------------------------------------------------------------
// 5) GEMM3 (dominant): y[b,n,o] = sum_ch w[o,ch] * agg[b,ch,n]  (tf32 TC)
// ---------------------------------------------------------------------------
__global__ void __launch_bounds__(256, 2) gemm3_k(const float* __restrict__ w) {
    __shared__ float As[32][LDS], Bs[32][LDS];
    int n0 = blockIdx.x * 128, o0 = blockIdx.y * 128, b = blockIdx.z;
    int tid = threadIdx.x;
    int wid = tid >> 5, wm = wid >> 1, wn = wid & 1;
    const float* A = g_att + b * CC * NN;  // [ch][n]
    FragC acc[2][4];
    #pragma unroll
    for (int mi = 0; mi < 2; mi++)
        #pragma unroll
        for (int ni = 0; ni < 4; ni++) wmma::fill_fragment(acc[mi][ni], 0.f);
    for (int it = 0; it < CC / 32; it++) {
        int k0 = it * 32;
        #pragma unroll
        for (int k = 0; k < 16; k++) {
            int e = tid + 256 * k; int tt = e & 127, kk = e >> 7;
            As[kk][tt] = A[(k0 + kk) * NN + n0 + tt];
        }
        #pragma unroll
        for (int k = 0; k < 16; k++) {
            int e = tid + 256 * k; int kk = e & 31, oo = e >> 5;
            Bs[kk][oo] = w[(o0 + oo) * CC + k0 + kk];
        }
        __syncthreads();
        wmma_tile(&As[0][0], &Bs[0][0], acc, wm, wn);
        __syncthreads();
    }
    float* out = g_y + (b * NN + n0) * OO + o0;
    store_tile(out, OO, acc, wm, wn);
}

// ---------------------------------------------------------------------------
// 6) Fused bias + LayerNorm over O=2048, one block per token
// ---------------------------------------------------------------------------
__global__ void ln_k(float* __restrict__ out, const float* __restrict__ bp,
                     const float* __restrict__ gm, const float* __restrict__ bt) {
    int t = blockIdx.x;
    const float* y = g_y + t * OO;
    int tid = threadIdx.x;
    float v[8];
    float s = 0.f, sq = 0.f;
    #pragma unroll
    for (int k = 0; k < 8; k++) {
        int o = tid + 256 * k;
        float x = y[o] + bp[o];
        v[k] = x; s += x; sq += x * x;
    }
    #pragma unroll
    for (int o = 16; o; o >>= 1) {
        s += __shfl_xor_sync(0xffffffffu, s, o);
        sq += __shfl_xor_sync(0xffffffffu, sq, o);
    }
    __shared__ float rs[8], rq[8];
    if ((tid & 31) == 0) { rs[tid >> 5] = s; rq[tid >> 5] = sq; }
    __syncthreads();
    if (tid < 8) {
        float a = rs[tid], b2 = rq[tid];
        #pragma unroll
        for (int o = 4; o; o >>= 1) {
            a += __shfl_xor_sync(0x000000ffu, a, o);
            b2 += __shfl_xor_sync(0x000000ffu, b2, o);
        }
        if (tid == 0) { rs[0] = a; rq[0] = b2; }
    }
    __syncthreads();
    float mean = rs[0] * (1.f / OO);
    float var = rq[0] * (1.f / OO) - mean * mean;
    float rstd = rsqrtf(var + 1e-5f);
    float* op = out + t * OO;
    #pragma unroll
    for (int k = 0; k < 8; k++) {
        int o = tid + 256 * k;
        op[o] = (v[k] - mean) * rstd * gm[o] + bt[o];
    }
}

extern "C" void kernel_launch(void* const* d_in, const int* in_sizes, int n_in,
                              void* d_out, int out_size) {
    const float* x1 = (const float*)d_in[0];
    const float* x2 = (const float*)d_in[1];
    const float* w  = (const float*)d_in[2];
    const float* bp = (const float*)d_in[3];
    const float* gm = (const float*)d_in[4];
    const float* bt = (const float*)d_in[5];
    float* out = (float*)d_out;

    colstats_k<<<dim3(CC / 32, BB), dim3(32, 8)>>>(x2);
    prep_k<<<dim3(NN / 32, BB), 256>>>(x1, x2);
    gemm1_k<<<dim3(NSEG, BB * NH), 256>>>();
    reduceS_k<<<(BB * NH * HC * HC) / 256, 256>>>();
    gemm2_k<<<dim3(NN / 128, BB * NH), 256>>>();
    gemm3_k<<<dim3(NN / 128, OO / 128, BB), 256>>>(w);
    ln_k<<<BB * NN, 256>>>(out, bp, gm, bt);
}

// round 4
// speedup vs baseline: 3.2989x; 2.5972x over previous
#include <cuda_runtime.h>
#include <cstdint>

#define BB 4
#define NN 4096
#define CC 1024
#define NH 8
#define HC 128
#define OO 2048
#define NSEG 8

// Scratch (device globals; no allocation allowed)
__device__ __align__(256) float g_Q[BB*CC*NN];
__device__ __align__(256) float g_K[BB*CC*NN];
__device__ __align__(256) float g_att[BB*NN*CC];   // token-major [b][n][C]
__device__ __align__(256) float g_S[BB*NH*HC*HC];
__device__ __align__(256) float g_Sp[NSEG*BB*NH*HC*HC];
__device__ __align__(256) float g_y[BB*NN*OO];
__device__ __align__(256) float g_wt[OO*CC];
__device__ float g_cmax[BB*CC];
__device__ float g_cinv[BB*CC];

// ---------------------------------------------------------------- helpers
__device__ __forceinline__ float tf32r(float x) {
    uint32_t b; asm("cvt.rna.tf32.f32 %0, %1;" : "=r"(b) : "f"(x));
    return __uint_as_float(b);
}
__device__ __forceinline__ uint32_t s2u(const void* p) {
    uint32_t a;
    asm("{ .reg .u64 t; cvta.to.shared.u64 t, %1; cvt.u32.u64 %0, t; }" : "=r"(a) : "l"(p));
    return a;
}
__device__ __forceinline__ void cp16(uint32_t d, const void* s) {
    asm volatile("cp.async.cg.shared.global [%0], [%1], 16;" :: "r"(d), "l"(s));
}
#define CP_COMMIT() asm volatile("cp.async.commit_group;" ::: "memory")
#define CP_WAIT0()  asm volatile("cp.async.wait_group 0;" ::: "memory")
#define CP_WAIT1()  asm volatile("cp.async.wait_group 1;" ::: "memory")
#define SWZ(o) ((o) ^ (((o) >> 3) & 0x70))

__device__ __forceinline__ void ldsm4(uint32_t* r, uint32_t addr) {
    asm volatile("ldmatrix.sync.aligned.m8n8.x4.shared.b16 {%0,%1,%2,%3}, [%4];"
        : "=r"(r[0]), "=r"(r[1]), "=r"(r[2]), "=r"(r[3]) : "r"(addr));
}
__device__ __forceinline__ void mma_tf32(float* c, const uint32_t* a, const uint32_t* b) {
    asm volatile("mma.sync.aligned.m16n8k8.row.col.f32.tf32.tf32.f32 "
        "{%0,%1,%2,%3}, {%4,%5,%6,%7}, {%8,%9}, {%0,%1,%2,%3};"
        : "+f"(c[0]), "+f"(c[1]), "+f"(c[2]), "+f"(c[3])
        : "r"(a[0]), "r"(a[1]), "r"(a[2]), "r"(a[3]), "r"(b[0]), "r"(b[1]));
}

// Warp computes 64(m) x 32(n) over one 128-float-wide k=32 tile pair.
// As[m][k] (m rows, 128B each, SW128), Bs[n][k] (n rows, 128B each, SW128).
__device__ __forceinline__ void warp_mma_tile(uint32_t sbA, uint32_t sbB, int wm, int wn,
                                              int lane, float (&acc)[4][4][4]) {
    int rA = (lane & 15), cA = (lane & 16) >> 2;           // row sel, +k offset (floats)
    int rB = (lane & 7) + ((lane & 16) >> 1), cB = (lane & 8) >> 1;
    #pragma unroll
    for (int k8 = 0; k8 < 4; k8++) {
        int k0 = k8 * 8;
        uint32_t a[4][4], b[2][4];
        #pragma unroll
        for (int mi = 0; mi < 4; mi++)
            ldsm4(a[mi], sbA + SWZ((wm * 64 + mi * 16 + rA) * 128 + (k0 + cA) * 4));
        #pragma unroll
        for (int nj = 0; nj < 2; nj++)
            ldsm4(b[nj], sbB + SWZ((wn * 32 + nj * 16 + rB) * 128 + (k0 + cB) * 4));
        #pragma unroll
        for (int mi = 0; mi < 4; mi++)
            #pragma unroll
            for (int ni = 0; ni < 4; ni++)
                mma_tf32(acc[mi][ni], a[mi], &b[ni >> 1][(ni & 1) * 2]);
    }
}

template <bool RND>
__device__ __forceinline__ void store_acc(float* out, int ld, float (&acc)[4][4][4],
                                          int wm, int wn, int lane) {
    int r0 = wm * 64 + (lane >> 2), col0 = wn * 32 + 2 * (lane & 3);
    #pragma unroll
    for (int mi = 0; mi < 4; mi++)
        #pragma unroll
        for (int ni = 0; ni < 4; ni++) {
            float* c = acc[mi][ni];
            float2 lo, hi;
            if (RND) {
                lo = make_float2(tf32r(c[0]), tf32r(c[1]));
                hi = make_float2(tf32r(c[2]), tf32r(c[3]));
            } else {
                lo = make_float2(c[0], c[1]);
                hi = make_float2(c[2], c[3]);
            }
            *(float2*)&out[(size_t)(r0 + mi * 16) * ld + col0 + ni * 8] = lo;
            *(float2*)&out[(size_t)(r0 + mi * 16 + 8) * ld + col0 + ni * 8] = hi;
        }
}

// ---------------------------------------------------------------------------
// 1) Column softmax stats for "key"
// ---------------------------------------------------------------------------
__global__ void colstats_k(const float* __restrict__ x2) {
    int b = blockIdx.y;
    int ch = blockIdx.x * 32 + threadIdx.x;
    const float* p = x2 + (size_t)b * NN * CC + ch;
    float m = -1e30f, s = 0.f;
    for (int n = threadIdx.y; n < NN; n += 8) {
        float v = p[(size_t)n * CC];
        float mn = fmaxf(m, v);
        s = s * __expf(m - mn) + __expf(v - mn);
        m = mn;
    }
    __shared__ float sm_[8][32], ss_[8][32];
    sm_[threadIdx.y][threadIdx.x] = m;
    ss_[threadIdx.y][threadIdx.x] = s;
    __syncthreads();
    if (threadIdx.y == 0) {
        for (int r = 1; r < 8; r++) {
            float m2 = sm_[r][threadIdx.x], s2 = ss_[r][threadIdx.x];
            float mn = fmaxf(m, m2);
            s = s * __expf(m - mn) + s2 * __expf(m2 - mn);
            m = mn;
        }
        g_cmax[b * CC + ch] = m;
        g_cinv[b * CC + ch] = 1.f / s;
    }
}

// ---------------------------------------------------------------------------
// 2) Prep: transpose + both softmaxes, write Q, K as [b,h,c,N], tf32-rounded
// ---------------------------------------------------------------------------
__global__ void prep_k(const float* __restrict__ x2) {
    __shared__ float t[HC][33];
    __shared__ float tmx[32], tsi[32];
    int b = blockIdx.y, n0 = blockIdx.x * 32;
    int tid = threadIdx.x;
    int w = tid >> 5, l = tid & 31;
    for (int hd = 0; hd < NH; hd++) {
        const float* src = x2 + ((size_t)(b * NN + n0)) * CC + hd * HC;
        #pragma unroll
        for (int k = 0; k < 16; k++) {
            int e = tid + 256 * k; int i = e & 127, tt = e >> 7;
            t[i][tt] = src[(size_t)tt * CC + i];
        }
        __syncthreads();
        #pragma unroll
        for (int q = 0; q < 4; q++) {
            int tok = w * 4 + q;
            float v0 = t[l][tok], v1 = t[l + 32][tok], v2 = t[l + 64][tok], v3 = t[l + 96][tok];
            float m = fmaxf(fmaxf(v0, v1), fmaxf(v2, v3));
            #pragma unroll
            for (int o = 16; o; o >>= 1) m = fmaxf(m, __shfl_xor_sync(0xffffffffu, m, o));
            float s = __expf(v0 - m) + __expf(v1 - m) + __expf(v2 - m) + __expf(v3 - m);
            #pragma unroll
            for (int o = 16; o; o >>= 1) s += __shfl_xor_sync(0xffffffffu, s, o);
            if (l == 0) { tmx[tok] = m; tsi[tok] = 1.f / s; }
        }
        __syncthreads();
        float* Qd = g_Q + ((size_t)(b * NH + hd)) * HC * NN + n0;
        float* Kd = g_K + ((size_t)(b * NH + hd)) * HC * NN + n0;
        const float* cm = g_cmax + b * CC + hd * HC;
        const float* ci = g_cinv + b * CC + hd * HC;
        #pragma unroll
        for (int k = 0; k < 16; k++) {
            int e = tid + 256 * k; int tt = e & 31, i = e >> 5;
            float v = t[i][tt];
            Qd[(size_t)i * NN + tt] = tf32r(__expf(v - tmx[tt]) * tsi[tt]);
            Kd[(size_t)i * NN + tt] = tf32r(__expf(v - cm[i]) * ci[i]);
        }
        __syncthreads();
    }
}

// ---------------------------------------------------------------------------
// 2b) Pre-round the projection weight to tf32
// ---------------------------------------------------------------------------
__global__ void roundw_k(const float* __restrict__ w) {
    int i = blockIdx.x * 256 + threadIdx.x;
    float4 v = ((const float4*)w)[i];
    v.x = tf32r(v.x); v.y = tf32r(v.y); v.z = tf32r(v.z); v.w = tf32r(v.w);
    ((float4*)g_wt)[i] = v;
}

// ---------------------------------------------------------------------------
// 3) GEMM1 (split-K): Sp[seg] = Q[:,seg] * K[:,seg]^T   M=128 N=128 K=512
// ---------------------------------------------------------------------------
__global__ void __launch_bounds__(256) gemm1_k() {
    extern __shared__ char smbuf[];
    uint32_t sb = s2u(smbuf);
    int tid = threadIdx.x, lane = tid & 31, wid = tid >> 5;
    int wm = wid >> 2, wn = wid & 3;
    int seg = blockIdx.x, bh = blockIdx.y;
    const float* Ag = g_Q + (size_t)bh * HC * NN;
    const float* Bg = g_K + (size_t)bh * HC * NN;
    int kbase = seg * (NN / NSEG);
    float acc[4][4][4] = {};
    // buffer layout: [buf][A 16KB][B 16KB]
    {
        for (int q = tid; q < 1024; q += 256) {
            int r = q >> 3, c = q & 7;
            cp16(sb + SWZ(r * 128 + c * 16), Ag + (size_t)r * NN + kbase + c * 4);
            cp16(sb + 16384 + SWZ(r * 128 + c * 16), Bg + (size_t)r * NN + kbase + c * 4);
        }
        CP_COMMIT();
    }
    for (int t = 0; t < 16; t++) {
        if (t + 1 < 16) {
            uint32_t nb = sb + ((t + 1) & 1) * 32768;
            int k0 = kbase + (t + 1) * 32;
            for (int q = tid; q < 1024; q += 256) {
                int r = q >> 3, c = q & 7;
                cp16(nb + SWZ(r * 128 + c * 16), Ag + (size_t)r * NN + k0 + c * 4);
                cp16(nb + 16384 + SWZ(r * 128 + c * 16), Bg + (size_t)r * NN + k0 + c * 4);
            }
            CP_COMMIT();
            CP_WAIT1();
        } else CP_WAIT0();
        __syncthreads();
        uint32_t cb = sb + (t & 1) * 32768;
        warp_mma_tile(cb, cb + 16384, wm, wn, lane, acc);
        __syncthreads();
    }
    float* out = g_Sp + ((size_t)(seg * BB * NH + bh)) * HC * HC;
    store_acc<false>(out, HC, acc, wm, wn, lane);
}

__global__ void reduceS_k() {
    int i = blockIdx.x * 256 + threadIdx.x;
    float s = 0.f;
    #pragma unroll
    for (int r = 0; r < NSEG; r++) s += g_Sp[(size_t)r * (BB * NH * HC * HC) + i];
    g_S[i] = tf32r(s);
}

// ---------------------------------------------------------------------------
// 4) GEMM2: att^T per (b,h):  att[tok][ch] = sum_j x1[tok][j] * S[ch][j]
//    M=128 tok, N=128 ch, K=128.  A = x1 rows (tf32-rounded on fill), B = S.
// ---------------------------------------------------------------------------
__global__ void __launch_bounds__(256) gemm2_k(const float* __restrict__ x1) {
    extern __shared__ char smbuf[];
    uint32_t sb = s2u(smbuf);
    int tid = threadIdx.x, lane = tid & 31, wid = tid >> 5;
    int wm = wid >> 2, wn = wid & 3;
    int tok0 = blockIdx.x * 128, bh = blockIdx.y;
    int b = bh >> 3, hd = bh & 7;
    const float* xA = x1 + ((size_t)(b * NN + tok0)) * CC + hd * HC;
    const float* Sg = g_S + (size_t)bh * HC * HC;
    float acc[4][4][4] = {};
    // prologue buf0
    for (int q = tid; q < 1024; q += 256) {
        int r = q >> 3, c = q & 7;
        float4 v = *(const float4*)(xA + (size_t)r * CC + c * 4);
        v.x = tf32r(v.x); v.y = tf32r(v.y); v.z = tf32r(v.z); v.w = tf32r(v.w);
        *(float4*)(smbuf + SWZ(r * 128 + c * 16)) = v;
        cp16(sb + 16384 + SWZ(r * 128 + c * 16), Sg + (size_t)r * HC + c * 4);
    }
    CP_COMMIT();
    for (int t = 0; t < 4; t++) {
        if (t + 1 < 4) {
            int k0 = (t + 1) * 32;
            char* nbp = smbuf + ((t + 1) & 1) * 32768;
            uint32_t nb = sb + ((t + 1) & 1) * 32768;
            for (int q = tid; q < 1024; q += 256) {
                int r = q >> 3, c = q & 7;
                float4 v = *(const float4*)(xA + (size_t)r * CC + k0 + c * 4);
                v.x = tf32r(v.x); v.y = tf32r(v.y); v.z = tf32r(v.z); v.w = tf32r(v.w);
                *(float4*)(nbp + SWZ(r * 128 + c * 16)) = v;
                cp16(nb + 16384 + SWZ(r * 128 + c * 16), Sg + (size_t)r * HC + k0 + c * 4);
            }
            CP_COMMIT();
            CP_WAIT1();
        } else CP_WAIT0();
        __syncthreads();
        uint32_t cb = sb + (t & 1) * 32768;
        warp_mma_tile(cb, cb + 16384, wm, wn, lane, acc);
        __syncthreads();
    }
    float* out = g_att + ((size_t)(b * NN + tok0)) * CC + hd * HC;
    store_acc<true>(out, CC, acc, wm, wn, lane);
}

// ---------------------------------------------------------------------------
// 5) GEMM3 (dominant): y[tokg][o] = sum_ch att[tokg][ch] * wt[o][ch]
//    M=128 tok, N=128 o, K=1024.
// ---------------------------------------------------------------------------
__global__ void __launch_bounds__(256) gemm3_k() {
    extern __shared__ char smbuf[];
    uint32_t sb = s2u(smbuf);
    int tid = threadIdx.x, lane = tid & 31, wid = tid >> 5;
    int wm = wid >> 2, wn = wid & 3;
    int m0 = blockIdx.x * 128, o0 = blockIdx.y * 128;
    const float* Ag = g_att + (size_t)m0 * CC;
    const float* Bg = g_wt + (size_t)o0 * CC;
    float acc[4][4][4] = {};
    for (int q = tid; q < 1024; q += 256) {
        int r = q >> 3, c = q & 7;
        cp16(sb + SWZ(r * 128 + c * 16), Ag + (size_t)r * CC + c * 4);
        cp16(sb + 16384 + SWZ(r * 128 + c * 16), Bg + (size_t)r * CC + c * 4);
    }
    CP_COMMIT();
    for (int t = 0; t < 32; t++) {
        if (t + 1 < 32) {
            int k0 = (t + 1) * 32;
            uint32_t nb = sb + ((t + 1) & 1) * 32768;
            for (int q = tid; q < 1024; q += 256) {
                int r = q >> 3, c = q & 7;
                cp16(nb + SWZ(r * 128 + c * 16), Ag + (size_t)r * CC + k0 + c * 4);
                cp16(nb + 16384 + SWZ(r * 128 + c * 16), Bg + (size_t)r * CC + k0 + c * 4);
            }
            CP_COMMIT();
            CP_WAIT1();
        } else CP_WAIT0();
        __syncthreads();
        uint32_t cb = sb + (t & 1) * 32768;
        warp_mma_tile(cb, cb + 16384, wm, wn, lane, acc);
        __syncthreads();
    }
    float* out = g_y + (size_t)m0 * OO + o0;
    store_acc<false>(out, OO, acc, wm, wn, lane);
}

// ---------------------------------------------------------------------------
// 6) Fused bias + LayerNorm over O=2048
// ---------------------------------------------------------------------------
__global__ void ln_k(float* __restrict__ out, const float* __restrict__ bp,
                     const float* __restrict__ gm, const float* __restrict__ bt) {
    int t = blockIdx.x;
    const float* y = g_y + (size_t)t * OO;
    int tid = threadIdx.x;
    float v[8];
    float s = 0.f, sq = 0.f;
    #pragma unroll
    for (int k = 0; k < 8; k++) {
        int o = tid + 256 * k;
        float x = y[o] + bp[o];
        v[k] = x; s += x; sq += x * x;
    }
    #pragma unroll
    for (int o = 16; o; o >>= 1) {
        s += __shfl_xor_sync(0xffffffffu, s, o);
        sq += __shfl_xor_sync(0xffffffffu, sq, o);
    }
    __shared__ float rs[8], rq[8];
    if ((tid & 31) == 0) { rs[tid >> 5] = s; rq[tid >> 5] = sq; }
    __syncthreads();
    if (tid < 8) {
        float a = rs[tid], b2 = rq[tid];
        #pragma unroll
        for (int o = 4; o; o >>= 1) {
            a += __shfl_xor_sync(0x000000ffu, a, o);
            b2 += __shfl_xor_sync(0x000000ffu, b2, o);
        }
        if (tid == 0) { rs[0] = a; rq[0] = b2; }
    }
    __syncthreads();
    float mean = rs[0] * (1.f / OO);
    float var = rq[0] * (1.f / OO) - mean * mean;
    float rstd = rsqrtf(var + 1e-5f);
    float* op = out + (size_t)t * OO;
    #pragma unroll
    for (int k = 0; k < 8; k++) {
        int o = tid + 256 * k;
        op[o] = (v[k] - mean) * rstd * gm[o] + bt[o];
    }
}

extern "C" void kernel_launch(void* const* d_in, const int* in_sizes, int n_in,
                              void* d_out, int out_size) {
    const float* x1 = (const float*)d_in[0];
    const float* x2 = (const float*)d_in[1];
    const float* w  = (const float*)d_in[2];
    const float* bp = (const float*)d_in[3];
    const float* gm = (const float*)d_in[4];
    const float* bt = (const float*)d_in[5];
    float* out = (float*)d_out;

    const int SMG = 65536;  // 2 x (16KB A + 16KB B)
    cudaFuncSetAttribute(gemm1_k, cudaFuncAttributeMaxDynamicSharedMemorySize, SMG);
    cudaFuncSetAttribute(gemm2_k, cudaFuncAttributeMaxDynamicSharedMemorySize, SMG);
    cudaFuncSetAttribute(gemm3_k, cudaFuncAttributeMaxDynamicSharedMemorySize, SMG);

    colstats_k<<<dim3(CC / 32, BB), dim3(32, 8)>>>(x2);
    prep_k<<<dim3(NN / 32, BB), 256>>>(x2);
    roundw_k<<<(OO * CC / 4) / 256, 256>>>(w);
    gemm1_k<<<dim3(NSEG, BB * NH), 256, SMG>>>();
    reduceS_k<<<(BB * NH * HC * HC) / 256, 256>>>();
    gemm2_k<<<dim3(NN / 128, BB * NH), 256, SMG>>>(x1);
    gemm3_k<<<dim3(BB * NN / 128, OO / 128), 256, SMG>>>();
    ln_k<<<BB * NN, 256>>>(out, bp, gm, bt);
}

// round 5
// speedup vs baseline: 3.3004x; 1.0005x over previous
#include <cuda_runtime.h>
#include <cstdint>

#define BB 4
#define NN 4096
#define CC 1024
#define NH 8
#define HC 128
#define OO 2048
#define NSEG 8

// Scratch (device globals; no allocation allowed)
__device__ __align__(256) float g_Q[BB*CC*NN];
__device__ __align__(256) float g_K[BB*CC*NN];
__device__ __align__(256) float g_x1r[BB*NN*CC];
__device__ __align__(256) float g_S[BB*NH*HC*HC];     // holds S^T[j][i]
__device__ __align__(256) float g_Sp[NSEG*BB*NH*HC*HC];
__device__ __align__(256) float g_T[BB*OO*CC];        // [b][o][c'] tf32
__device__ __align__(256) float g_y[BB*NN*OO];
__device__ __align__(256) float g_wt[OO*CC];
__device__ float g_cmax[BB*CC];
__device__ float g_cinv[BB*CC];

// ---------------------------------------------------------------- helpers
__device__ __forceinline__ float tf32r(float x) {
    uint32_t b; asm("cvt.rna.tf32.f32 %0, %1;" : "=r"(b) : "f"(x));
    return __uint_as_float(b);
}
__device__ __forceinline__ uint32_t s2u(const void* p) {
    uint32_t a;
    asm("{ .reg .u64 t; cvta.to.shared.u64 t, %1; cvt.u32.u64 %0, t; }" : "=r"(a) : "l"(p));
    return a;
}
__device__ __forceinline__ void cp16(uint32_t d, const void* s) {
    asm volatile("cp.async.cg.shared.global [%0], [%1], 16;" :: "r"(d), "l"(s));
}
#define CP_COMMIT() asm volatile("cp.async.commit_group;" ::: "memory")
#define CP_WAIT0()  asm volatile("cp.async.wait_group 0;" ::: "memory")
#define CP_WAIT1()  asm volatile("cp.async.wait_group 1;" ::: "memory")
#define SWZ(o) ((o) ^ (((o) >> 3) & 0x70))

__device__ __forceinline__ void ldsm4(uint32_t* r, uint32_t addr) {
    asm volatile("ldmatrix.sync.aligned.m8n8.x4.shared.b16 {%0,%1,%2,%3}, [%4];"
        : "=r"(r[0]), "=r"(r[1]), "=r"(r[2]), "=r"(r[3]) : "r"(addr));
}
__device__ __forceinline__ void mma_tf32(float* c, const uint32_t* a, const uint32_t* b) {
    asm volatile("mma.sync.aligned.m16n8k8.row.col.f32.tf32.tf32.f32 "
        "{%0,%1,%2,%3}, {%4,%5,%6,%7}, {%8,%9}, {%0,%1,%2,%3};"
        : "+f"(c[0]), "+f"(c[1]), "+f"(c[2]), "+f"(c[3])
        : "r"(a[0]), "r"(a[1]), "r"(a[2]), "r"(a[3]), "r"(b[0]), "r"(b[1]));
}

// 64(m) x 32(n) warp tile over k=32 (for gemm1/gemmT)
__device__ __forceinline__ void warp_mma_tile(uint32_t sbA, uint32_t sbB, int wm, int wn,
                                              int lane, float (&acc)[4][4][4]) {
    int rA = (lane & 15), cA = (lane & 16) >> 2;
    int rB = (lane & 7) + ((lane & 16) >> 1), cB = (lane & 8) >> 1;
    #pragma unroll
    for (int k8 = 0; k8 < 4; k8++) {
        int k0 = k8 * 8;
        uint32_t a[4][4], b[2][4];
        #pragma unroll
        for (int mi = 0; mi < 4; mi++)
            ldsm4(a[mi], sbA + SWZ((wm * 64 + mi * 16 + rA) * 128 + (k0 + cA) * 4));
        #pragma unroll
        for (int nj = 0; nj < 2; nj++)
            ldsm4(b[nj], sbB + SWZ((wn * 32 + nj * 16 + rB) * 128 + (k0 + cB) * 4));
        #pragma unroll
        for (int mi = 0; mi < 4; mi++)
            #pragma unroll
            for (int ni = 0; ni < 4; ni++)
                mma_tf32(acc[mi][ni], a[mi], &b[ni >> 1][(ni & 1) * 2]);
    }
}

template <bool RND>
__device__ __forceinline__ void store_acc(float* out, int ld, float (&acc)[4][4][4],
                                          int wm, int wn, int lane) {
    int r0 = wm * 64 + (lane >> 2), col0 = wn * 32 + 2 * (lane & 3);
    #pragma unroll
    for (int mi = 0; mi < 4; mi++)
        #pragma unroll
        for (int ni = 0; ni < 4; ni++) {
            float* c = acc[mi][ni];
            float2 lo, hi;
            if (RND) {
                lo = make_float2(tf32r(c[0]), tf32r(c[1]));
                hi = make_float2(tf32r(c[2]), tf32r(c[3]));
            } else {
                lo = make_float2(c[0], c[1]);
                hi = make_float2(c[2], c[3]);
            }
            *(float2*)&out[(size_t)(r0 + mi * 16) * ld + col0 + ni * 8] = lo;
            *(float2*)&out[(size_t)(r0 + mi * 16 + 8) * ld + col0 + ni * 8] = hi;
        }
}

// 64(m) x 64(n) warp tile over k=32 (for gemmF)
__device__ __forceinline__ void warp_mma64(uint32_t sbA, uint32_t sbB, int wm, int wn,
                                           int lane, float (&acc)[4][8][4]) {
    int rA = (lane & 15), cA = (lane & 16) >> 2;
    int rB = (lane & 7) + ((lane & 16) >> 1), cB = (lane & 8) >> 1;
    #pragma unroll
    for (int k8 = 0; k8 < 4; k8++) {
        int k0 = k8 * 8;
        uint32_t a[4][4], b[4][4];
        #pragma unroll
        for (int mi = 0; mi < 4; mi++)
            ldsm4(a[mi], sbA + SWZ((wm * 64 + mi * 16 + rA) * 128 + (k0 + cA) * 4));
        #pragma unroll
        for (int nj = 0; nj < 4; nj++)
            ldsm4(b[nj], sbB + SWZ((wn * 64 + nj * 16 + rB) * 128 + (k0 + cB) * 4));
        #pragma unroll
        for (int mi = 0; mi < 4; mi++)
            #pragma unroll
            for (int ni = 0; ni < 8; ni++)
                mma_tf32(acc[mi][ni], a[mi], &b[ni >> 1][(ni & 1) * 2]);
    }
}

__device__ __forceinline__ void store_acc64(float* out, int ld, float (&acc)[4][8][4],
                                            int wm, int wn, int lane) {
    int r0 = wm * 64 + (lane >> 2), col0 = wn * 64 + 2 * (lane & 3);
    #pragma unroll
    for (int mi = 0; mi < 4; mi++)
        #pragma unroll
        for (int ni = 0; ni < 8; ni++) {
            float* c = acc[mi][ni];
            *(float2*)&out[(size_t)(r0 + mi * 16) * ld + col0 + ni * 8] = make_float2(c[0], c[1]);
            *(float2*)&out[(size_t)(r0 + mi * 16 + 8) * ld + col0 + ni * 8] = make_float2(c[2], c[3]);
        }
}

// ---------------------------------------------------------------------------
// 1) Column softmax stats for "key"
// ---------------------------------------------------------------------------
__global__ void colstats_k(const float* __restrict__ x2) {
    int b = blockIdx.y;
    int ch = blockIdx.x * 32 + threadIdx.x;
    const float* p = x2 + (size_t)b * NN * CC + ch;
    float m = -1e30f, s = 0.f;
    for (int n = threadIdx.y; n < NN; n += 8) {
        float v = p[(size_t)n * CC];
        float mn = fmaxf(m, v);
        s = s * __expf(m - mn) + __expf(v - mn);
        m = mn;
    }
    __shared__ float sm_[8][32], ss_[8][32];
    sm_[threadIdx.y][threadIdx.x] = m;
    ss_[threadIdx.y][threadIdx.x] = s;
    __syncthreads();
    if (threadIdx.y == 0) {
        for (int r = 1; r < 8; r++) {
            float m2 = sm_[r][threadIdx.x], s2 = ss_[r][threadIdx.x];
            float mn = fmaxf(m, m2);
            s = s * __expf(m - mn) + s2 * __expf(m2 - mn);
            m = mn;
        }
        g_cmax[b * CC + ch] = m;
        g_cinv[b * CC + ch] = 1.f / s;
    }
}

// ---------------------------------------------------------------------------
// 2) Prep: transpose + both softmaxes, write Q, K as [b,h,c,N], tf32-rounded
// ---------------------------------------------------------------------------
__global__ void prep_k(const float* __restrict__ x2) {
    __shared__ float t[HC][33];
    __shared__ float tmx[32], tsi[32];
    int b = blockIdx.y, n0 = blockIdx.x * 32;
    int tid = threadIdx.x;
    int w = tid >> 5, l = tid & 31;
    for (int hd = 0; hd < NH; hd++) {
        const float* src = x2 + ((size_t)(b * NN + n0)) * CC + hd * HC;
        #pragma unroll
        for (int k = 0; k < 16; k++) {
            int e = tid + 256 * k; int i = e & 127, tt = e >> 7;
            t[i][tt] = src[(size_t)tt * CC + i];
        }
        __syncthreads();
        #pragma unroll
        for (int q = 0; q < 4; q++) {
            int tok = w * 4 + q;
            float v0 = t[l][tok], v1 = t[l + 32][tok], v2 = t[l + 64][tok], v3 = t[l + 96][tok];
            float m = fmaxf(fmaxf(v0, v1), fmaxf(v2, v3));
            #pragma unroll
            for (int o = 16; o; o >>= 1) m = fmaxf(m, __shfl_xor_sync(0xffffffffu, m, o));
            float s = __expf(v0 - m) + __expf(v1 - m) + __expf(v2 - m) + __expf(v3 - m);
            #pragma unroll
            for (int o = 16; o; o >>= 1) s += __shfl_xor_sync(0xffffffffu, s, o);
            if (l == 0) { tmx[tok] = m; tsi[tok] = 1.f / s; }
        }
        __syncthreads();
        float* Qd = g_Q + ((size_t)(b * NH + hd)) * HC * NN + n0;
        float* Kd = g_K + ((size_t)(b * NH + hd)) * HC * NN + n0;
        const float* cm = g_cmax + b * CC + hd * HC;
        const float* ci = g_cinv + b * CC + hd * HC;
        #pragma unroll
        for (int k = 0; k < 16; k++) {
            int e = tid + 256 * k; int tt = e & 31, i = e >> 5;
            float v = t[i][tt];
            Qd[(size_t)i * NN + tt] = tf32r(__expf(v - tmx[tt]) * tsi[tt]);
            Kd[(size_t)i * NN + tt] = tf32r(__expf(v - cm[i]) * ci[i]);
        }
        __syncthreads();
    }
}

// ---------------------------------------------------------------------------
// 2b) Pre-round w and x1 to tf32
// ---------------------------------------------------------------------------
__global__ void roundw_k(const float* __restrict__ w) {
    int i = blockIdx.x * 256 + threadIdx.x;
    float4 v = ((const float4*)w)[i];
    v.x = tf32r(v.x); v.y = tf32r(v.y); v.z = tf32r(v.z); v.w = tf32r(v.w);
    ((float4*)g_wt)[i] = v;
}
__global__ void roundx1_k(const float* __restrict__ x1) {
    int i = blockIdx.x * 256 + threadIdx.x;
    float4 v = ((const float4*)x1)[i];
    v.x = tf32r(v.x); v.y = tf32r(v.y); v.z = tf32r(v.z); v.w = tf32r(v.w);
    ((float4*)g_x1r)[i] = v;
}

// ---------------------------------------------------------------------------
// 3) GEMM1 (split-K): Sp^T[seg][j][i] = K_j . Q_i   M=128(j) N=128(i) K=512
// ---------------------------------------------------------------------------
__global__ void __launch_bounds__(256) gemm1_k() {
    extern __shared__ char smbuf[];
    uint32_t sb = s2u(smbuf);
    int tid = threadIdx.x, lane = tid & 31, wid = tid >> 5;
    int wm = wid >> 2, wn = wid & 3;
    int seg = blockIdx.x, bh = blockIdx.y;
    const float* Ag = g_K + (size_t)bh * HC * NN;   // A rows -> j
    const float* Bg = g_Q + (size_t)bh * HC * NN;   // B rows -> i
    int kbase = seg * (NN / NSEG);
    float acc[4][4][4] = {};
    for (int q = tid; q < 1024; q += 256) {
        int r = q >> 3, c = q & 7;
        cp16(sb + SWZ(r * 128 + c * 16), Ag + (size_t)r * NN + kbase + c * 4);
        cp16(sb + 16384 + SWZ(r * 128 + c * 16), Bg + (size_t)r * NN + kbase + c * 4);
    }
    CP_COMMIT();
    for (int t = 0; t < 16; t++) {
        if (t + 1 < 16) {
            uint32_t nb = sb + ((t + 1) & 1) * 32768;
            int k0 = kbase + (t + 1) * 32;
            for (int q = tid; q < 1024; q += 256) {
                int r = q >> 3, c = q & 7;
                cp16(nb + SWZ(r * 128 + c * 16), Ag + (size_t)r * NN + k0 + c * 4);
                cp16(nb + 16384 + SWZ(r * 128 + c * 16), Bg + (size_t)r * NN + k0 + c * 4);
            }
            CP_COMMIT();
            CP_WAIT1();
        } else CP_WAIT0();
        __syncthreads();
        uint32_t cb = sb + (t & 1) * 32768;
        warp_mma_tile(cb, cb + 16384, wm, wn, lane, acc);
        __syncthreads();
    }
    float* out = g_Sp + ((size_t)(seg * BB * NH + bh)) * HC * HC;
    store_acc<false>(out, HC, acc, wm, wn, lane);
}

__global__ void reduceS_k() {
    int i = blockIdx.x * 256 + threadIdx.x;
    float s = 0.f;
    #pragma unroll
    for (int r = 0; r < NSEG; r++) s += g_Sp[(size_t)r * (BB * NH * HC * HC) + i];
    g_S[i] = tf32r(s);
}

// ---------------------------------------------------------------------------
// 4) GEMMT: T[b][o][h*128+j] = sum_c w[o, h*128+c] * S[c,j]
//    A = wt rows (o, k=c), B = S^T rows (j, k=c).  M=128 N=128 K=128
// ---------------------------------------------------------------------------
__global__ void __launch_bounds__(256) gemmT_k() {
    extern __shared__ char smbuf[];
    uint32_t sb = s2u(smbuf);
    int tid = threadIdx.x, lane = tid & 31, wid = tid >> 5;
    int wm = wid >> 2, wn = wid & 3;
    int o0 = blockIdx.x * 128, bh = blockIdx.y;
    int b = bh >> 3, hd = bh & 7;
    const float* Ag = g_wt + (size_t)o0 * CC + hd * HC;   // row stride CC
    const float* Bg = g_S + (size_t)bh * HC * HC;         // row stride HC
    float acc[4][4][4] = {};
    for (int q = tid; q < 1024; q += 256) {
        int r = q >> 3, c = q & 7;
        cp16(sb + SWZ(r * 128 + c * 16), Ag + (size_t)r * CC + c * 4);
        cp16(sb + 16384 + SWZ(r * 128 + c * 16), Bg + (size_t)r * HC + c * 4);
    }
    CP_COMMIT();
    for (int t = 0; t < 4; t++) {
        if (t + 1 < 4) {
            int k0 = (t + 1) * 32;
            uint32_t nb = sb + ((t + 1) & 1) * 32768;
            for (int q = tid; q < 1024; q += 256) {
                int r = q >> 3, c = q & 7;
                cp16(nb + SWZ(r * 128 + c * 16), Ag + (size_t)r * CC + k0 + c * 4);
                cp16(nb + 16384 + SWZ(r * 128 + c * 16), Bg + (size_t)r * HC + k0 + c * 4);
            }
            CP_COMMIT();
            CP_WAIT1();
        } else CP_WAIT0();
        __syncthreads();
        uint32_t cb = sb + (t & 1) * 32768;
        warp_mma_tile(cb, cb + 16384, wm, wn, lane, acc);
        __syncthreads();
    }
    float* out = g_T + ((size_t)b * OO + o0) * CC + hd * HC;
    store_acc<true>(out, CC, acc, wm, wn, lane);
}

// ---------------------------------------------------------------------------
// 5) GEMMF (dominant): y[n][o] = sum_c' x1r[n][c'] * T[b][o][c']
//    M=128(tok) N=256(o) K=1024, warp tile 64x64
// ---------------------------------------------------------------------------
__global__ void __launch_bounds__(256, 1) gemmF_k() {
    extern __shared__ char smbuf[];
    uint32_t sb = s2u(smbuf);
    int tid = threadIdx.x, lane = tid & 31, wid = tid >> 5;
    int wm = wid & 1, wn = wid >> 1;
    int m0 = blockIdx.x * 128, o0 = blockIdx.y * 256;
    int b = m0 >> 12;
    const float* Ag = g_x1r + (size_t)m0 * CC;
    const float* Bg = g_T + ((size_t)b * OO + o0) * CC;
    float acc[4][8][4] = {};
    // buffers: buf stride 49152; A @ +0 (16KB), B @ +16384 (32KB)
    for (int q = tid; q < 1024; q += 256) {
        int r = q >> 3, c = q & 7;
        cp16(sb + SWZ(r * 128 + c * 16), Ag + (size_t)r * CC + c * 4);
    }
    for (int q = tid; q < 2048; q += 256) {
        int r = q >> 3, c = q & 7;
        cp16(sb + 16384 + SWZ(r * 128 + c * 16), Bg + (size_t)r * CC + c * 4);
    }
    CP_COMMIT();
    for (int t = 0; t < 32; t++) {
        if (t + 1 < 32) {
            int k0 = (t + 1) * 32;
            uint32_t nb = sb + ((t + 1) & 1) * 49152;
            for (int q = tid; q < 1024; q += 256) {
                int r = q >> 3, c = q & 7;
                cp16(nb + SWZ(r * 128 + c * 16), Ag + (size_t)r * CC + k0 + c * 4);
            }
            for (int q = tid; q < 2048; q += 256) {
                int r = q >> 3, c = q & 7;
                cp16(nb + 16384 + SWZ(r * 128 + c * 16), Bg + (size_t)r * CC + k0 + c * 4);
            }
            CP_COMMIT();
            CP_WAIT1();
        } else CP_WAIT0();
        __syncthreads();
        uint32_t cb = sb + (t & 1) * 49152;
        warp_mma64(cb, cb + 16384, wm, wn, lane, acc);
        __syncthreads();
    }
    float* out = g_y + (size_t)m0 * OO + o0;
    store_acc64(out, OO, acc, wm, wn, lane);
}

// ---------------------------------------------------------------------------
// 6) Fused bias + LayerNorm over O=2048
// ---------------------------------------------------------------------------
__global__ void ln_k(float* __restrict__ out, const float* __restrict__ bp,
                     const float* __restrict__ gm, const float* __restrict__ bt) {
    int t = blockIdx.x;
    const float* y = g_y + (size_t)t * OO;
    int tid = threadIdx.x;
    float v[8];
    float s = 0.f, sq = 0.f;
    #pragma unroll
    for (int k = 0; k < 8; k++) {
        int o = tid + 256 * k;
        float x = y[o] + bp[o];
        v[k] = x; s += x; sq += x * x;
    }
    #pragma unroll
    for (int o = 16; o; o >>= 1) {
        s += __shfl_xor_sync(0xffffffffu, s, o);
        sq += __shfl_xor_sync(0xffffffffu, sq, o);
    }
    __shared__ float rs[8], rq[8];
    if ((tid & 31) == 0) { rs[tid >> 5] = s; rq[tid >> 5] = sq; }
    __syncthreads();
    if (tid < 8) {
        float a = rs[tid], b2 = rq[tid];
        #pragma unroll
        for (int o = 4; o; o >>= 1) {
            a += __shfl_xor_sync(0x000000ffu, a, o);
            b2 += __shfl_xor_sync(0x000000ffu, b2, o);
        }
        if (tid == 0) { rs[0] = a; rq[0] = b2; }
    }
    __syncthreads();
    float mean = rs[0] * (1.f / OO);
    float var = rq[0] * (1.f / OO) - mean * mean;
    float rstd = rsqrtf(var + 1e-5f);
    float* op = out + (size_t)t * OO;
    #pragma unroll
    for (int k = 0; k < 8; k++) {
        int o = tid + 256 * k;
        op[o] = (v[k] - mean) * rstd * gm[o] + bt[o];
    }
}

extern "C" void kernel_launch(void* const* d_in, const int* in_sizes, int n_in,
                              void* d_out, int out_size) {
    const float* x1 = (const float*)d_in[0];
    const float* x2 = (const float*)d_in[1];
    const float* w  = (const float*)d_in[2];
    const float* bp = (const float*)d_in[3];
    const float* gm = (const float*)d_in[4];
    const float* bt = (const float*)d_in[5];
    float* out = (float*)d_out;

    const int SMG = 65536;   // gemm1/gemmT: 2 x (16KB + 16KB)
    const int SMF = 98304;   // gemmF: 2 x (16KB + 32KB)
    cudaFuncSetAttribute(gemm1_k, cudaFuncAttributeMaxDynamicSharedMemorySize, SMG);
    cudaFuncSetAttribute(gemmT_k, cudaFuncAttributeMaxDynamicSharedMemorySize, SMG);
    cudaFuncSetAttribute(gemmF_k, cudaFuncAttributeMaxDynamicSharedMemorySize, SMF);

    colstats_k<<<dim3(CC / 32, BB), dim3(32, 8)>>>(x2);
    prep_k<<<dim3(NN / 32, BB), 256>>>(x2);
    roundw_k<<<(OO * CC / 4) / 256, 256>>>(w);
    roundx1_k<<<(BB * NN * CC / 4) / 256, 256>>>(x1);
    gemm1_k<<<dim3(NSEG, BB * NH), 256, SMG>>>();
    reduceS_k<<<(BB * NH * HC * HC) / 256, 256>>>();
    gemmT_k<<<dim3(OO / 128, BB * NH), 256, SMG>>>();
    gemmF_k<<<dim3(BB * NN / 128, OO / 256), 256, SMF>>>();
    ln_k<<<BB * NN, 256>>>(out, bp, gm, bt);
}

// round 6
// speedup vs baseline: 5.0879x; 1.5416x over previous
#include <cuda_runtime.h>
#include <cuda_fp16.h>
#include <cstdint>

#define BB 4
#define NN 4096
#define CC 1024
#define NH 8
#define HC 128
#define OO 2048
#define NSEG 8

// Scratch (device globals; no allocation allowed)
__device__ __align__(256) __half g_Qh[BB*CC*NN];
__device__ __align__(256) __half g_Kh[BB*CC*NN];
__device__ __align__(256) __half g_x1h[BB*NN*CC];
__device__ __align__(256) __half g_Sh[BB*NH*HC*HC];    // S^T[j][i] fp16
__device__ __align__(256) float  g_Sp[NSEG*BB*NH*HC*HC];
__device__ __align__(256) __half g_Th[BB*OO*CC];       // [b][o][c'] fp16
__device__ __align__(256) __half g_yh[BB*NN*OO];
__device__ __align__(256) __half g_wh[OO*CC];
__device__ float g_cmax[BB*CC];
__device__ float g_cinv[BB*CC];

// ---------------------------------------------------------------- helpers
__device__ __forceinline__ uint32_t s2u(const void* p) {
    uint32_t a;
    asm("{ .reg .u64 t; cvta.to.shared.u64 t, %1; cvt.u32.u64 %0, t; }" : "=r"(a) : "l"(p));
    return a;
}
__device__ __forceinline__ void cp16(uint32_t d, const void* s) {
    asm volatile("cp.async.cg.shared.global [%0], [%1], 16;" :: "r"(d), "l"(s));
}
#define CP_COMMIT() asm volatile("cp.async.commit_group;" ::: "memory")
#define CP_WAIT0()  asm volatile("cp.async.wait_group 0;" ::: "memory")
#define CP_WAIT1()  asm volatile("cp.async.wait_group 1;" ::: "memory")
#define SWZ(o) ((o) ^ (((o) >> 3) & 0x70))

__device__ __forceinline__ void ldsm4(uint32_t* r, uint32_t addr) {
    asm volatile("ldmatrix.sync.aligned.m8n8.x4.shared.b16 {%0,%1,%2,%3}, [%4];"
        : "=r"(r[0]), "=r"(r[1]), "=r"(r[2]), "=r"(r[3]) : "r"(addr));
}
__device__ __forceinline__ void mma_h(float* c, const uint32_t* a, const uint32_t* b) {
    asm volatile("mma.sync.aligned.m16n8k16.row.col.f32.f16.f16.f32 "
        "{%0,%1,%2,%3}, {%4,%5,%6,%7}, {%8,%9}, {%0,%1,%2,%3};"
        : "+f"(c[0]), "+f"(c[1]), "+f"(c[2]), "+f"(c[3])
        : "r"(a[0]), "r"(a[1]), "r"(a[2]), "r"(a[3]), "r"(b[0]), "r"(b[1]));
}

// fp16 warp tile 64(m) x 64(n) over one k=64 tile (rows = 128B = 64 halves, SW128)
__device__ __forceinline__ void warp_mma_h64(uint32_t sbA, uint32_t sbB, int wm, int wn,
                                             int lane, float (&acc)[4][8][4]) {
    int rA = lane & 15, cA = (lane & 16);               // +16B for lanes 16-31
    int rB = (lane & 7) + ((lane & 16) >> 1), cB = (lane & 8) << 1;
    #pragma unroll
    for (int s = 0; s < 4; s++) {                        // k16 steps, 32B each
        uint32_t a[4][4], b[4][4];
        #pragma unroll
        for (int mi = 0; mi < 4; mi++)
            ldsm4(a[mi], sbA + SWZ((wm * 64 + mi * 16 + rA) * 128 + s * 32 + cA));
        #pragma unroll
        for (int nj = 0; nj < 4; nj++)
            ldsm4(b[nj], sbB + SWZ((wn * 64 + nj * 16 + rB) * 128 + s * 32 + cB));
        #pragma unroll
        for (int mi = 0; mi < 4; mi++)
            #pragma unroll
            for (int ni = 0; ni < 8; ni++)
                mma_h(acc[mi][ni], a[mi], &b[ni >> 1][(ni & 1) * 2]);
    }
}

__device__ __forceinline__ void store_acc64f(float* out, int ld, float (&acc)[4][8][4],
                                             int wm, int wn, int lane) {
    int r0 = wm * 64 + (lane >> 2), col0 = wn * 64 + 2 * (lane & 3);
    #pragma unroll
    for (int mi = 0; mi < 4; mi++)
        #pragma unroll
        for (int ni = 0; ni < 8; ni++) {
            float* c = acc[mi][ni];
            *(float2*)&out[(size_t)(r0 + mi * 16) * ld + col0 + ni * 8] = make_float2(c[0], c[1]);
            *(float2*)&out[(size_t)(r0 + mi * 16 + 8) * ld + col0 + ni * 8] = make_float2(c[2], c[3]);
        }
}
__device__ __forceinline__ void store_acc64h(__half* out, int ld, float (&acc)[4][8][4],
                                             int wm, int wn, int lane) {
    int r0 = wm * 64 + (lane >> 2), col0 = wn * 64 + 2 * (lane & 3);
    #pragma unroll
    for (int mi = 0; mi < 4; mi++)
        #pragma unroll
        for (int ni = 0; ni < 8; ni++) {
            float* c = acc[mi][ni];
            *(__half2*)&out[(size_t)(r0 + mi * 16) * ld + col0 + ni * 8] = __floats2half2_rn(c[0], c[1]);
            *(__half2*)&out[(size_t)(r0 + mi * 16 + 8) * ld + col0 + ni * 8] = __floats2half2_rn(c[2], c[3]);
        }
}

// ---------------------------------------------------------------------------
// 1) Column softmax stats for "key"
// ---------------------------------------------------------------------------
__global__ void colstats_k(const float* __restrict__ x2) {
    int b = blockIdx.y;
    int ch = blockIdx.x * 32 + threadIdx.x;
    const float* p = x2 + (size_t)b * NN * CC + ch;
    float m = -1e30f, s = 0.f;
    for (int n = threadIdx.y; n < NN; n += 8) {
        float v = p[(size_t)n * CC];
        float mn = fmaxf(m, v);
        s = s * __expf(m - mn) + __expf(v - mn);
        m = mn;
    }
    __shared__ float sm_[8][32], ss_[8][32];
    sm_[threadIdx.y][threadIdx.x] = m;
    ss_[threadIdx.y][threadIdx.x] = s;
    __syncthreads();
    if (threadIdx.y == 0) {
        for (int r = 1; r < 8; r++) {
            float m2 = sm_[r][threadIdx.x], s2 = ss_[r][threadIdx.x];
            float mn = fmaxf(m, m2);
            s = s * __expf(m - mn) + s2 * __expf(m2 - mn);
            m = mn;
        }
        g_cmax[b * CC + ch] = m;
        g_cinv[b * CC + ch] = 1.f / s;
    }
}

// ---------------------------------------------------------------------------
// 2) Prep: transpose + both softmaxes, write Q, K as [b,h,c,N] fp16
// ---------------------------------------------------------------------------
__global__ void prep_k(const float* __restrict__ x2) {
    __shared__ float t[HC][33];
    __shared__ float tmx[32], tsi[32];
    int b = blockIdx.y, n0 = blockIdx.x * 32;
    int tid = threadIdx.x;
    int w = tid >> 5, l = tid & 31;
    for (int hd = 0; hd < NH; hd++) {
        const float* src = x2 + ((size_t)(b * NN + n0)) * CC + hd * HC;
        #pragma unroll
        for (int k = 0; k < 16; k++) {
            int e = tid + 256 * k; int i = e & 127, tt = e >> 7;
            t[i][tt] = src[(size_t)tt * CC + i];
        }
        __syncthreads();
        #pragma unroll
        for (int q = 0; q < 4; q++) {
            int tok = w * 4 + q;
            float v0 = t[l][tok], v1 = t[l + 32][tok], v2 = t[l + 64][tok], v3 = t[l + 96][tok];
            float m = fmaxf(fmaxf(v0, v1), fmaxf(v2, v3));
            #pragma unroll
            for (int o = 16; o; o >>= 1) m = fmaxf(m, __shfl_xor_sync(0xffffffffu, m, o));
            float s = __expf(v0 - m) + __expf(v1 - m) + __expf(v2 - m) + __expf(v3 - m);
            #pragma unroll
            for (int o = 16; o; o >>= 1) s += __shfl_xor_sync(0xffffffffu, s, o);
            if (l == 0) { tmx[tok] = m; tsi[tok] = 1.f / s; }
        }
        __syncthreads();
        __half* Qd = g_Qh + ((size_t)(b * NH + hd)) * HC * NN + n0;
        __half* Kd = g_Kh + ((size_t)(b * NH + hd)) * HC * NN + n0;
        const float* cm = g_cmax + b * CC + hd * HC;
        const float* ci = g_cinv + b * CC + hd * HC;
        #pragma unroll
        for (int k = 0; k < 8; k++) {
            int e = tid + 256 * k;            // 2048 half2 elements
            int tp = (e & 15) * 2, i = e >> 4;
            float va = t[i][tp], vb = t[i][tp + 1];
            float qa = __expf(va - tmx[tp]) * tsi[tp];
            float qb = __expf(vb - tmx[tp + 1]) * tsi[tp + 1];
            float ka = __expf(va - cm[i]) * ci[i];
            float kb = __expf(vb - cm[i]) * ci[i];
            *(__half2*)(Qd + (size_t)i * NN + tp) = __floats2half2_rn(qa, qb);
            *(__half2*)(Kd + (size_t)i * NN + tp) = __floats2half2_rn(ka, kb);
        }
        __syncthreads();
    }
}

// ---------------------------------------------------------------------------
// 2b) Convert w and x1 to fp16
// ---------------------------------------------------------------------------
__global__ void cvtw_k(const float* __restrict__ w) {
    int i = blockIdx.x * 256 + threadIdx.x;
    float4 v = ((const float4*)w)[i];
    ((__half2*)g_wh)[2 * i] = __floats2half2_rn(v.x, v.y);
    ((__half2*)g_wh)[2 * i + 1] = __floats2half2_rn(v.z, v.w);
}
__global__ void cvtx1_k(const float* __restrict__ x1) {
    int i = blockIdx.x * 256 + threadIdx.x;
    float4 v = ((const float4*)x1)[i];
    ((__half2*)g_x1h)[2 * i] = __floats2half2_rn(v.x, v.y);
    ((__half2*)g_x1h)[2 * i + 1] = __floats2half2_rn(v.z, v.w);
}

// ---------------------------------------------------------------------------
// 3) GEMM1 (split-K): Sp^T[seg][j][i] = K_j . Q_i   M=128(j) N=128(i) K=512
//    128 threads (4 warps, 2x2 of 64x64)
// ---------------------------------------------------------------------------
__global__ void __launch_bounds__(128) gemm1_k() {
    extern __shared__ char smbuf[];
    uint32_t sb = s2u(smbuf);
    int tid = threadIdx.x, lane = tid & 31, wid = tid >> 5;
    int wm = wid >> 1, wn = wid & 1;
    int seg = blockIdx.x, bh = blockIdx.y;
    const __half* Ag = g_Kh + (size_t)bh * HC * NN;
    const __half* Bg = g_Qh + (size_t)bh * HC * NN;
    int kbase = seg * (NN / NSEG);
    float acc[4][8][4] = {};
    // buffer: [buf 32KB][A 16KB][B 16KB]
    for (int q = tid; q < 1024; q += 128) {
        int r = q >> 3, c = q & 7;
        cp16(sb + SWZ(r * 128 + c * 16), Ag + (size_t)r * NN + kbase + c * 8);
        cp16(sb + 16384 + SWZ(r * 128 + c * 16), Bg + (size_t)r * NN + kbase + c * 8);
    }
    CP_COMMIT();
    for (int t = 0; t < 8; t++) {
        if (t + 1 < 8) {
            uint32_t nb = sb + ((t + 1) & 1) * 32768;
            int k0 = kbase + (t + 1) * 64;
            for (int q = tid; q < 1024; q += 128) {
                int r = q >> 3, c = q & 7;
                cp16(nb + SWZ(r * 128 + c * 16), Ag + (size_t)r * NN + k0 + c * 8);
                cp16(nb + 16384 + SWZ(r * 128 + c * 16), Bg + (size_t)r * NN + k0 + c * 8);
            }
            CP_COMMIT();
            CP_WAIT1();
        } else CP_WAIT0();
        __syncthreads();
        uint32_t cb = sb + (t & 1) * 32768;
        warp_mma_h64(cb, cb + 16384, wm, wn, lane, acc);
        __syncthreads();
    }
    float* out = g_Sp + ((size_t)(seg * BB * NH + bh)) * HC * HC;
    store_acc64f(out, HC, acc, wm, wn, lane);
}

__global__ void reduceS_k() {
    int i = blockIdx.x * 256 + threadIdx.x;
    float s = 0.f;
    #pragma unroll
    for (int r = 0; r < NSEG; r++) s += g_Sp[(size_t)r * (BB * NH * HC * HC) + i];
    g_Sh[i] = __float2half_rn(s);
}

// ---------------------------------------------------------------------------
// 4) GEMMT: T[b][o][h*128+j] = sum_c w[o, h*128+c] * S[c,j]
//    A = wh rows (o, k=c) stride CC, B = S^T rows (j, k=c) stride HC.
//    M=128 N=128 K=128, 128 threads
// ---------------------------------------------------------------------------
__global__ void __launch_bounds__(128) gemmT_k() {
    extern __shared__ char smbuf[];
    uint32_t sb = s2u(smbuf);
    int tid = threadIdx.x, lane = tid & 31, wid = tid >> 5;
    int wm = wid >> 1, wn = wid & 1;
    int o0 = blockIdx.x * 128, bh = blockIdx.y;
    int b = bh >> 3, hd = bh & 7;
    const __half* Ag = g_wh + (size_t)o0 * CC + hd * HC;
    const __half* Bg = g_Sh + (size_t)bh * HC * HC;
    float acc[4][8][4] = {};
    for (int q = tid; q < 1024; q += 128) {
        int r = q >> 3, c = q & 7;
        cp16(sb + SWZ(r * 128 + c * 16), Ag + (size_t)r * CC + c * 8);
        cp16(sb + 16384 + SWZ(r * 128 + c * 16), Bg + (size_t)r * HC + c * 8);
    }
    CP_COMMIT();
    for (int t = 0; t < 2; t++) {
        if (t + 1 < 2) {
            int k0 = (t + 1) * 64;
            uint32_t nb = sb + 32768;
            for (int q = tid; q < 1024; q += 128) {
                int r = q >> 3, c = q & 7;
                cp16(nb + SWZ(r * 128 + c * 16), Ag + (size_t)r * CC + k0 + c * 8);
                cp16(nb + 16384 + SWZ(r * 128 + c * 16), Bg + (size_t)r * HC + k0 + c * 8);
            }
            CP_COMMIT();
            CP_WAIT1();
        } else CP_WAIT0();
        __syncthreads();
        uint32_t cb = sb + (t & 1) * 32768;
        warp_mma_h64(cb, cb + 16384, wm, wn, lane, acc);
        __syncthreads();
    }
    __half* out = g_Th + ((size_t)b * OO + o0) * CC + hd * HC;
    store_acc64h(out, CC, acc, wm, wn, lane);
}

// ---------------------------------------------------------------------------
// 5) GEMMF (dominant): y[n][o] = sum_c' x1h[n][c'] * T[b][o][c']
//    M=128(tok) N=256(o) K=1024, 256 threads, warp tile 64x64
// ---------------------------------------------------------------------------
__global__ void __launch_bounds__(256) gemmF_k() {
    extern __shared__ char smbuf[];
    uint32_t sb = s2u(smbuf);
    int tid = threadIdx.x, lane = tid & 31, wid = tid >> 5;
    int wm = wid & 1, wn = wid >> 1;
    int m0 = blockIdx.x * 128, o0 = blockIdx.y * 256;
    int b = m0 >> 12;
    const __half* Ag = g_x1h + (size_t)m0 * CC;
    const __half* Bg = g_Th + ((size_t)b * OO + o0) * CC;
    float acc[4][8][4] = {};
    // buffers: stride 49152; A @ +0 (16KB), B @ +16384 (32KB)
    for (int q = tid; q < 1024; q += 256) {
        int r = q >> 3, c = q & 7;
        cp16(sb + SWZ(r * 128 + c * 16), Ag + (size_t)r * CC + c * 8);
    }
    for (int q = tid; q < 2048; q += 256) {
        int r = q >> 3, c = q & 7;
        cp16(sb + 16384 + SWZ(r * 128 + c * 16), Bg + (size_t)r * CC + c * 8);
    }
    CP_COMMIT();
    for (int t = 0; t < 16; t++) {
        if (t + 1 < 16) {
            int k0 = (t + 1) * 64;
            uint32_t nb = sb + ((t + 1) & 1) * 49152;
            for (int q = tid; q < 1024; q += 256) {
                int r = q >> 3, c = q & 7;
                cp16(nb + SWZ(r * 128 + c * 16), Ag + (size_t)r * CC + k0 + c * 8);
            }
            for (int q = tid; q < 2048; q += 256) {
                int r = q >> 3, c = q & 7;
                cp16(nb + 16384 + SWZ(r * 128 + c * 16), Bg + (size_t)r * CC + k0 + c * 8);
            }
            CP_COMMIT();
            CP_WAIT1();
        } else CP_WAIT0();
        __syncthreads();
        uint32_t cb = sb + (t & 1) * 49152;
        warp_mma_h64(cb, cb + 16384, wm, wn, lane, acc);
        __syncthreads();
    }
    __half* out = g_yh + (size_t)m0 * OO + o0;
    store_acc64h(out, OO, acc, wm, wn, lane);
}

// ---------------------------------------------------------------------------
// 6) Fused bias + LayerNorm over O=2048 (reads fp16 y)
// ---------------------------------------------------------------------------
__global__ void ln_k(float* __restrict__ out, const float* __restrict__ bp,
                     const float* __restrict__ gm, const float* __restrict__ bt) {
    int t = blockIdx.x;
    const __half2* y2 = (const __half2*)(g_yh + (size_t)t * OO);
    int tid = threadIdx.x;
    float v[8];
    float s = 0.f, sq = 0.f;
    #pragma unroll
    for (int k = 0; k < 4; k++) {
        int idx = tid + 256 * k;              // half2 index, o = 2*idx
        float2 xv = __half22float2(y2[idx]);
        float xa = xv.x + bp[2 * idx], xb = xv.y + bp[2 * idx + 1];
        v[2 * k] = xa; v[2 * k + 1] = xb;
        s += xa + xb; sq += xa * xa + xb * xb;
    }
    #pragma unroll
    for (int o = 16; o; o >>= 1) {
        s += __shfl_xor_sync(0xffffffffu, s, o);
        sq += __shfl_xor_sync(0xffffffffu, sq, o);
    }
    __shared__ float rs[8], rq[8];
    if ((tid & 31) == 0) { rs[tid >> 5] = s; rq[tid >> 5] = sq; }
    __syncthreads();
    if (tid < 8) {
        float a = rs[tid], b2 = rq[tid];
        #pragma unroll
        for (int o = 4; o; o >>= 1) {
            a += __shfl_xor_sync(0x000000ffu, a, o);
            b2 += __shfl_xor_sync(0x000000ffu, b2, o);
        }
        if (tid == 0) { rs[0] = a; rq[0] = b2; }
    }
    __syncthreads();
    float mean = rs[0] * (1.f / OO);
    float var = rq[0] * (1.f / OO) - mean * mean;
    float rstd = rsqrtf(var + 1e-5f);
    float* op = out + (size_t)t * OO;
    #pragma unroll
    for (int k = 0; k < 4; k++) {
        int idx = tid + 256 * k;
        int o = 2 * idx;
        float2 r = make_float2((v[2 * k] - mean) * rstd * gm[o] + bt[o],
                               (v[2 * k + 1] - mean) * rstd * gm[o + 1] + bt[o + 1]);
        *(float2*)&op[o] = r;
    }
}

extern "C" void kernel_launch(void* const* d_in, const int* in_sizes, int n_in,
                              void* d_out, int out_size) {
    const float* x1 = (const float*)d_in[0];
    const float* x2 = (const float*)d_in[1];
    const float* w  = (const float*)d_in[2];
    const float* bp = (const float*)d_in[3];
    const float* gm = (const float*)d_in[4];
    const float* bt = (const float*)d_in[5];
    float* out = (float*)d_out;

    const int SMG = 65536;   // gemm1/gemmT: 2 x (16KB + 16KB)
    const int SMF = 98304;   // gemmF: 2 x (16KB + 32KB)
    cudaFuncSetAttribute(gemm1_k, cudaFuncAttributeMaxDynamicSharedMemorySize, SMG);
    cudaFuncSetAttribute(gemmT_k, cudaFuncAttributeMaxDynamicSharedMemorySize, SMG);
    cudaFuncSetAttribute(gemmF_k, cudaFuncAttributeMaxDynamicSharedMemorySize, SMF);

    colstats_k<<<dim3(CC / 32, BB), dim3(32, 8)>>>(x2);
    prep_k<<<dim3(NN / 32, BB), 256>>>(x2);
    cvtw_k<<<(OO * CC / 4) / 256, 256>>>(w);
    cvtx1_k<<<(BB * NN * CC / 4) / 256, 256>>>(x1);
    gemm1_k<<<dim3(NSEG, BB * NH), 128, SMG>>>();
    reduceS_k<<<(BB * NH * HC * HC) / 256, 256>>>();
    gemmT_k<<<dim3(OO / 128, BB * NH), 128, SMG>>>();
    gemmF_k<<<dim3(BB * NN / 128, OO / 256), 256, SMF>>>();
    ln_k<<<BB * NN, 256>>>(out, bp, gm, bt);
}